// round 13
// baseline (speedup 1.0000x reference)
#include <cuda_runtime.h>

typedef unsigned long long ull;

#define N_TOK 343
#define N_PAD 344                       /* padded j-dim: row 343 = dummy */
#define DIMM  192
#define NH    6
#define HD    32
#define BATCH 256
#define NWIN  64
#define M_ROWS (BATCH * N_TOK)          /* 87808 = 343 * 256 */
/* Q scale with log2(e) folded in: softmax uses ex2 */
#define QS_LOG2E (0.17677669529663687f * 1.4426950408889634f)
#define LOG2E    1.4426950408889634f

/* ------------------------------------------------------------------ */
/* Device scratch (no allocation allowed -> __device__ globals)        */
/* ------------------------------------------------------------------ */
__device__ float g_q[(size_t)BATCH * NH * N_TOK * HD];
__device__ float g_k[(size_t)BATCH * NH * N_TOK * HD];
__device__ float g_v[(size_t)BATCH * NH * N_TOK * HD];
__device__ float g_ao[(size_t)M_ROWS * DIMM];
/* bias*log2e, [h][j(344)][i(343)], row j=343 = -inf.  2.8 MB (L2)     */
__device__ float g_biasF[(size_t)NH * N_PAD * N_TOK + 8192];
/* mask*log2e, [w][j(344)][i(343)], row j=343 = 0.    30.2 MB (L2)     */
__device__ float g_maskT[(size_t)NWIN * N_PAD * N_TOK + 8192];

/* ------------------------------------------------------------------ */
/* f32x2 packed-math helpers (sm_103a)                                 */
/* ------------------------------------------------------------------ */
__device__ __forceinline__ ull fma2(ull a, ull b, ull c) {
    ull d;
    asm("fma.rn.f32x2 %0, %1, %2, %3;" : "=l"(d) : "l"(a), "l"(b), "l"(c));
    return d;
}
__device__ __forceinline__ ull add2(ull a, ull b) {
    ull d;
    asm("add.rn.f32x2 %0, %1, %2;" : "=l"(d) : "l"(a), "l"(b));
    return d;
}
__device__ __forceinline__ ull dup2(float x) {
    ull r;
    asm("mov.b64 %0, {%1, %1};" : "=l"(r) : "f"(x));
    return r;
}
__device__ __forceinline__ float2 u2f(ull x) {
    float2 r;
    asm("mov.b64 {%0, %1}, %2;" : "=f"(r.x), "=f"(r.y) : "l"(x));
    return r;
}
__device__ __forceinline__ float hsum2(ull a, ull b) {
    float2 f = u2f(add2(a, b));
    return f.x + f.y;
}
__device__ __forceinline__ float ex2f(float x) {
    float y;
    asm("ex2.approx.f32 %0, %1;" : "=f"(y) : "f"(x));
    return y;
}

/* ------------------------------------------------------------------ */
/* Kernel 0a: transpose mask -> [w][j][i] scaled by log2e; j=343 -> 0  */
/* ------------------------------------------------------------------ */
__global__ void transpose_mask_kernel(const float* __restrict__ mask) {
    __shared__ float t[32][33];
    int w = blockIdx.z;
    int j0 = blockIdx.x * 32, i0 = blockIdx.y * 32;
    int tx = threadIdx.x, ty = threadIdx.y;
#pragma unroll
    for (int k = 0; k < 32; k += 8) {
        int i = i0 + ty + k, j = j0 + tx;
        if (i < N_TOK && j < N_TOK)
            t[ty + k][tx] = mask[((size_t)w * N_TOK + i) * N_TOK + j];
    }
    __syncthreads();
#pragma unroll
    for (int k = 0; k < 32; k += 8) {
        int j = j0 + ty + k, i = i0 + tx;
        if (i < N_TOK) {
            if (j < N_TOK)
                g_maskT[((size_t)w * N_PAD + j) * N_TOK + i] = t[tx][ty + k] * LOG2E;
            else if (j == N_TOK)
                g_maskT[((size_t)w * N_PAD + j) * N_TOK + i] = 0.f;
        }
    }
}

/* ------------------------------------------------------------------ */
/* Kernel 0b: bias*log2e -> g_biasF[h][j][i]; j=343 row = -inf         */
/* ------------------------------------------------------------------ */
__global__ void build_bias_kernel(const float* __restrict__ table) {
    int i = threadIdx.x;   /* query 0..342 */
    int j = blockIdx.x;    /* key   0..343 */

    if (j == N_TOK) {
        float ninf = __int_as_float(0xff800000);
#pragma unroll
        for (int h = 0; h < NH; ++h)
            g_biasF[((size_t)h * N_PAD + N_TOK) * N_TOK + i] = ninf;
        return;
    }
    int di = i / 49, hi = (i / 7) % 7, wi = i % 7;
    int dj = j / 49, hj = (j / 7) % 7, wj = j % 7;
    int idx = (di - dj + 6) * 169 + (hi - hj + 6) * 13 + (wi - wj + 6);
#pragma unroll
    for (int h = 0; h < NH; ++h) {
        float b = __ldg(table + idx * NH + h);
        g_biasF[((size_t)h * N_PAD + j) * N_TOK + i] = b * LOG2E;
    }
}

/* ------------------------------------------------------------------ */
/* GEMM: Y[M, NN] = A[M,192] @ W[NN,192]^T + bias                      */
/*   BM=256, BN=64, BK=32, 256 threads, micro 16m x 4n (8 m-pairs)     */
/* ------------------------------------------------------------------ */
__global__ __launch_bounds__(256, 2) void gemm_kernel(
    const float* __restrict__ A_in, const float* __restrict__ W,
    const float* __restrict__ bias, float* __restrict__ outp, int mode)
{
    __shared__ __align__(16) float As[32][260];
    __shared__ __align__(16) float Bs[32][68];

    const float* A = (mode == 0) ? A_in : g_ao;
    int tid = threadIdx.x;
    int tn = tid & 15, tm = tid >> 4;
    size_t m0 = (size_t)blockIdx.x * 256;
    int n0 = blockIdx.y * 64;

    ull acc[8][4];
#pragma unroll
    for (int i = 0; i < 8; ++i)
#pragma unroll
        for (int j = 0; j < 4; ++j) acc[i][j] = 0ULL;

    for (int kt = 0; kt < 6; ++kt) {
        int k0 = kt * 32;
#pragma unroll
        for (int it = 0; it < 8; ++it) {
            int fid = tid + it * 256;
            int ml = fid >> 3, kc = fid & 7;
            float4 v = *(const float4*)(A + (m0 + ml) * DIMM + k0 + kc * 4);
            As[kc * 4 + 0][ml] = v.x;
            As[kc * 4 + 1][ml] = v.y;
            As[kc * 4 + 2][ml] = v.z;
            As[kc * 4 + 3][ml] = v.w;
        }
#pragma unroll
        for (int it = 0; it < 2; ++it) {
            int fid = tid + it * 256;
            int nl = fid >> 3, kc = fid & 7;
            float4 v = *(const float4*)(W + (size_t)(n0 + nl) * DIMM + k0 + kc * 4);
            Bs[kc * 4 + 0][nl] = v.x;
            Bs[kc * 4 + 1][nl] = v.y;
            Bs[kc * 4 + 2][nl] = v.z;
            Bs[kc * 4 + 3][nl] = v.w;
        }
        __syncthreads();
#pragma unroll
        for (int k = 0; k < 32; ++k) {
            const ulonglong2* ap = (const ulonglong2*)&As[k][tm * 16];
            ull a2[8];
#pragma unroll
            for (int c = 0; c < 4; ++c) {
                ulonglong2 t = ap[c];
                a2[2 * c] = t.x; a2[2 * c + 1] = t.y;
            }
            float4 bv = *(const float4*)&Bs[k][tn * 4];
            ull b0 = dup2(bv.x), b1 = dup2(bv.y), b2 = dup2(bv.z), b3 = dup2(bv.w);
#pragma unroll
            for (int i = 0; i < 8; ++i) {
                acc[i][0] = fma2(a2[i], b0, acc[i][0]);
                acc[i][1] = fma2(a2[i], b1, acc[i][1]);
                acc[i][2] = fma2(a2[i], b2, acc[i][2]);
                acc[i][3] = fma2(a2[i], b3, acc[i][3]);
            }
        }
        __syncthreads();
    }

    /* epilogue */
    int c0 = n0 + tn * 4;
    int which = c0 / DIMM;
    int rem = c0 - which * DIMM;
    int hh = rem >> 5;
    int d0 = rem & 31;
    float qs = (which == 0) ? QS_LOG2E : 1.0f;
    float* dst = (which == 0) ? g_q : ((which == 1) ? g_k : g_v);
    float bvs[4];
#pragma unroll
    for (int j = 0; j < 4; ++j) bvs[j] = bias[c0 + j];

#pragma unroll
    for (int i = 0; i < 8; ++i) {
        size_t mA = m0 + tm * 16 + 2 * i;
        if (mode == 1) {
#pragma unroll
            for (int j = 0; j < 4; ++j) {
                float2 v = u2f(acc[i][j]);
                outp[mA * DIMM + c0 + j] = v.x + bvs[j];
                outp[(mA + 1) * DIMM + c0 + j] = v.y + bvs[j];
            }
        } else {
            int b1 = (int)(mA / N_TOK), n1 = (int)(mA - (size_t)b1 * N_TOK);
            size_t r2 = mA + 1;
            int b2 = (int)(r2 / N_TOK), n2 = (int)(r2 - (size_t)b2 * N_TOK);
            size_t o1 = (((size_t)b1 * NH + hh) * N_TOK + n1) * HD + d0;
            size_t o2 = (((size_t)b2 * NH + hh) * N_TOK + n2) * HD + d0;
#pragma unroll
            for (int j = 0; j < 4; ++j) {
                float2 v = u2f(acc[i][j]);
                dst[o1 + j] = (v.x + bvs[j]) * qs;
                dst[o2 + j] = (v.y + bvs[j]) * qs;
            }
        }
    }
}

/* ------------------------------------------------------------------ */
/* Attention: one CTA per (b,h); K,V staged in smem with a zero pad    */
/* row at j=343 (88.1KB). 176 threads; thread t owns query rows t and  */
/* t+176. 86 uniform iterations of 4 keys; bias (L2, 2.8MB) and mask   */
/* (L2, 30MB), both *log2e, register-prefetched 4..8 keys ahead        */
/* (~480cyc >> L2 hit ~250cyc). softmax = ex2. Dummy key 343:          */
/* bias=-inf, mask=0, K/V row zero -> p=0.                             */
/* ------------------------------------------------------------------ */
__global__ __launch_bounds__(176, 2) void attn_kernel() {
    extern __shared__ float sm[];
    float* ks = sm;
    float* vs = sm + N_PAD * HD;

    int tid = threadIdx.x;
    int bh = blockIdx.x;
    int bb = bh / NH;
    int hh = bh - bb * NH;
    int w = bb & (NWIN - 1);

    size_t base = ((size_t)bb * NH + hh) * N_TOK * HD;

    { /* stage K and V + zero pad row, coalesced */
        const float4* ksrc = (const float4*)(g_k + base);
        const float4* vsrc = (const float4*)(g_v + base);
        float4* kdst = (float4*)ks;
        float4* vdst = (float4*)vs;
        const float4 z = make_float4(0.f, 0.f, 0.f, 0.f);
        for (int i = tid; i < N_PAD * HD / 4; i += 176) {
            bool in = (i < N_TOK * HD / 4);
            kdst[i] = in ? ksrc[i] : z;
            vdst[i] = in ? vsrc[i] : z;
        }
    }
    __syncthreads();

    int rA = tid;                       /* always < 343 */
    bool hasB = (tid < N_TOK - 176);    /* tid < 167 */
    int rB = hasB ? tid + 176 : tid;    /* alias A when inactive */

    const float* pbA = g_biasF + (size_t)hh * (N_PAD * N_TOK) + rA;
    const float* pbB = g_biasF + (size_t)hh * (N_PAD * N_TOK) + rB;
    const float* pmA = g_maskT + (size_t)w * (N_PAD * N_TOK) + rA;
    const float* pmB = g_maskT + (size_t)w * (N_PAD * N_TOK) + rB;

    ull qA[16], qB[16], oA[16], oB[16];
    {
        const ulonglong2* qa = (const ulonglong2*)(g_q + base + (size_t)rA * HD);
        const ulonglong2* qb = (const ulonglong2*)(g_q + base + (size_t)rB * HD);
#pragma unroll
        for (int c = 0; c < 8; ++c) {
            ulonglong2 ta = qa[c], tb = qb[c];
            qA[2 * c] = ta.x; qA[2 * c + 1] = ta.y;
            qB[2 * c] = tb.x; qB[2 * c + 1] = tb.y;
        }
    }
#pragma unroll
    for (int c = 0; c < 16; ++c) { oA[c] = 0ULL; oB[c] = 0ULL; }
    float lA = 0.f, lB = 0.f;

    /* rolling register prefetch of bias+mask, depth 4..8 keys */
    float curA[4], curB[4], nxtA[4], nxtB[4];
#pragma unroll
    for (int t = 0; t < 4; ++t) {
        curA[t] = __ldg(pbA + t * N_TOK) + __ldg(pmA + t * N_TOK);
        curB[t] = __ldg(pbB + t * N_TOK) + __ldg(pmB + t * N_TOK);
    }

    int koff = 0;
    for (int o = 0; o < N_PAD / 4; ++o) {          /* 86 iterations */
        int jpf = (o * 4 + 4) * N_TOK;
#pragma unroll
        for (int t = 0; t < 4; ++t) {
            nxtA[t] = __ldg(pbA + jpf + t * N_TOK) + __ldg(pmA + jpf + t * N_TOK);
            nxtB[t] = __ldg(pbB + jpf + t * N_TOK) + __ldg(pmB + jpf + t * N_TOK);
        }
#pragma unroll
        for (int jj = 0; jj < 4; ++jj) {
            const ulonglong2* kr = (const ulonglong2*)(ks + koff);
            ull dA0 = 0, dA1 = 0, dB0 = 0, dB1 = 0;
#pragma unroll
            for (int c = 0; c < 8; ++c) {
                ulonglong2 t = kr[c];
                dA0 = fma2(qA[2 * c],     t.x, dA0);
                dA1 = fma2(qA[2 * c + 1], t.y, dA1);
                dB0 = fma2(qB[2 * c],     t.x, dB0);
                dB1 = fma2(qB[2 * c + 1], t.y, dB1);
            }
            float sA = hsum2(dA0, dA1) + curA[jj];
            float sB = hsum2(dB0, dB1) + curB[jj];
            float pAx = ex2f(sA);
            float pBx = ex2f(sB);
            lA += pAx; lB += pBx;
            ull pA2 = dup2(pAx), pB2 = dup2(pBx);

            const ulonglong2* vr = (const ulonglong2*)(vs + koff);
#pragma unroll
            for (int c = 0; c < 8; ++c) {
                ulonglong2 t = vr[c];
                oA[2 * c]     = fma2(pA2, t.x, oA[2 * c]);
                oA[2 * c + 1] = fma2(pA2, t.y, oA[2 * c + 1]);
                oB[2 * c]     = fma2(pB2, t.x, oB[2 * c]);
                oB[2 * c + 1] = fma2(pB2, t.y, oB[2 * c + 1]);
            }
            koff += HD;
        }
#pragma unroll
        for (int t = 0; t < 4; ++t) { curA[t] = nxtA[t]; curB[t] = nxtB[t]; }
    }

    {
        float inv = 1.0f / lA;
        float4* dp = (float4*)(g_ao + ((size_t)bb * N_TOK + rA) * DIMM + hh * HD);
#pragma unroll
        for (int c = 0; c < 8; ++c) {
            float2 p0 = u2f(oA[2 * c]), p1 = u2f(oA[2 * c + 1]);
            dp[c] = make_float4(p0.x * inv, p0.y * inv, p1.x * inv, p1.y * inv);
        }
    }
    if (hasB) {
        float inv = 1.0f / lB;
        float4* dp = (float4*)(g_ao + ((size_t)bb * N_TOK + rB) * DIMM + hh * HD);
#pragma unroll
        for (int c = 0; c < 8; ++c) {
            float2 p0 = u2f(oB[2 * c]), p1 = u2f(oB[2 * c + 1]);
            dp[c] = make_float4(p0.x * inv, p0.y * inv, p1.x * inv, p1.y * inv);
        }
    }
}

/* ------------------------------------------------------------------ */
extern "C" void kernel_launch(void* const* d_in, const int* in_sizes, int n_in,
                              void* d_out, int out_size) {
    const float* x      = (const float*)d_in[0];
    const float* mask   = (const float*)d_in[1];
    const float* qkv_w  = (const float*)d_in[2];
    const float* qkv_b  = (const float*)d_in[3];
    const float* rpb    = (const float*)d_in[4];
    const float* proj_w = (const float*)d_in[5];
    const float* proj_b = (const float*)d_in[6];
    float* out = (float*)d_out;

    const int smem_attn = N_PAD * 2 * HD * sizeof(float);  /* 88064 B */
    cudaFuncSetAttribute(attn_kernel,
                         cudaFuncAttributeMaxDynamicSharedMemorySize, smem_attn);

    transpose_mask_kernel<<<dim3(11, 11, NWIN), dim3(32, 8)>>>(mask);
    build_bias_kernel<<<N_PAD, N_TOK>>>(rpb);
    gemm_kernel<<<dim3(M_ROWS / 256, 9), 256>>>(x, qkv_w, qkv_b, nullptr, 0);
    attn_kernel<<<BATCH * NH, 176, smem_attn>>>();
    gemm_kernel<<<dim3(M_ROWS / 256, 3), 256>>>(nullptr, proj_w, proj_b, out, 1);
}

// round 14
// speedup vs baseline: 1.0260x; 1.0260x over previous
#include <cuda_runtime.h>

typedef unsigned long long ull;

#define N_TOK 343
#define N_PAD 344                       /* j=343 = dummy key (-inf bias) */
#define N_EXT 345                       /* smem K/V rows incl. pipeline pad */
#define DIMM  192
#define NH    6
#define HD    32
#define BATCH 256
#define NWIN  64
#define M_ROWS (BATCH * N_TOK)          /* 87808 = 343 * 256 */
/* Q scale with log2(e) folded in: softmax uses ex2 */
#define QS_LOG2E (0.17677669529663687f * 1.4426950408889634f)
#define LOG2E    1.4426950408889634f

/* ------------------------------------------------------------------ */
/* Device scratch (no allocation allowed -> __device__ globals)        */
/* ------------------------------------------------------------------ */
__device__ float g_q[(size_t)BATCH * NH * N_TOK * HD];
__device__ float g_k[(size_t)BATCH * NH * N_TOK * HD];
__device__ float g_v[(size_t)BATCH * NH * N_TOK * HD];
__device__ float g_ao[(size_t)M_ROWS * DIMM];
__device__ float g_maskT[(size_t)NWIN * N_TOK * N_TOK];   /* [w][j][i] */
/* fused (bias+mask)*log2e, [h*64+w][j(344)][i(343)]; row j=343 = -inf.
   +2048 pad covers prefetch overrun on the last slice. */
__device__ float g_bm[(size_t)NH * NWIN * N_PAD * N_TOK + 2048];

/* ------------------------------------------------------------------ */
/* f32x2 packed-math helpers (sm_103a)                                 */
/* ------------------------------------------------------------------ */
__device__ __forceinline__ ull fma2(ull a, ull b, ull c) {
    ull d;
    asm("fma.rn.f32x2 %0, %1, %2, %3;" : "=l"(d) : "l"(a), "l"(b), "l"(c));
    return d;
}
__device__ __forceinline__ ull add2(ull a, ull b) {
    ull d;
    asm("add.rn.f32x2 %0, %1, %2;" : "=l"(d) : "l"(a), "l"(b));
    return d;
}
__device__ __forceinline__ ull dup2(float x) {
    ull r;
    asm("mov.b64 %0, {%1, %1};" : "=l"(r) : "f"(x));
    return r;
}
__device__ __forceinline__ float2 u2f(ull x) {
    float2 r;
    asm("mov.b64 {%0, %1}, %2;" : "=f"(r.x), "=f"(r.y) : "l"(x));
    return r;
}
__device__ __forceinline__ float hsum2(ull a, ull b) {
    float2 f = u2f(add2(a, b));
    return f.x + f.y;
}
__device__ __forceinline__ float ex2f(float x) {
    float y;
    asm("ex2.approx.f32 %0, %1;" : "=f"(y) : "f"(x));
    return y;
}

/* ------------------------------------------------------------------ */
/* Kernel 0a: transpose mask -> [w][j][i]                              */
/* ------------------------------------------------------------------ */
__global__ void transpose_mask_kernel(const float* __restrict__ mask) {
    __shared__ float t[32][33];
    int w = blockIdx.z;
    int j0 = blockIdx.x * 32, i0 = blockIdx.y * 32;
    int tx = threadIdx.x, ty = threadIdx.y;
#pragma unroll
    for (int k = 0; k < 32; k += 8) {
        int i = i0 + ty + k, j = j0 + tx;
        if (i < N_TOK && j < N_TOK)
            t[ty + k][tx] = mask[((size_t)w * N_TOK + i) * N_TOK + j];
    }
    __syncthreads();
#pragma unroll
    for (int k = 0; k < 32; k += 8) {
        int j = j0 + ty + k, i = i0 + tx;
        if (i < N_TOK && j < N_TOK)
            g_maskT[((size_t)w * N_TOK + j) * N_TOK + i] = t[tx][ty + k];
    }
}

/* ------------------------------------------------------------------ */
/* Kernel 0b: fuse (bias + mask)*log2e into g_bm[h*64+w][j][i];        */
/* row j=343 = -inf (dummy key column -> exp contributes 0).           */
/* ------------------------------------------------------------------ */
__global__ void combine_bm_kernel(const float* __restrict__ table) {
    int i = threadIdx.x;   /* query 0..342 */
    int j = blockIdx.x;    /* key   0..343 */
    int w = blockIdx.y;    /* 0..63 */

    if (j == N_TOK) {
        float ninf = __int_as_float(0xff800000);
#pragma unroll
        for (int h = 0; h < NH; ++h)
            g_bm[(((size_t)h * NWIN + w) * N_PAD + N_TOK) * N_TOK + i] = ninf;
        return;
    }
    int di = i / 49, hi = (i / 7) % 7, wi = i % 7;
    int dj = j / 49, hj = (j / 7) % 7, wj = j % 7;
    int idx = (di - dj + 6) * 169 + (hi - hj + 6) * 13 + (wi - wj + 6);
    float m = g_maskT[((size_t)w * N_TOK + j) * N_TOK + i];
#pragma unroll
    for (int h = 0; h < NH; ++h) {
        float b = __ldg(table + idx * NH + h);
        g_bm[(((size_t)h * NWIN + w) * N_PAD + j) * N_TOK + i] = (b + m) * LOG2E;
    }
}

/* ------------------------------------------------------------------ */
/* GEMM: Y[M, NN] = A[M,192] @ W[NN,192]^T + bias                      */
/*   BM=256, BN=64, BK=32, 256 threads, micro 16m x 4n (8 m-pairs)     */
/* ------------------------------------------------------------------ */
__global__ __launch_bounds__(256, 2) void gemm_kernel(
    const float* __restrict__ A_in, const float* __restrict__ W,
    const float* __restrict__ bias, float* __restrict__ outp, int mode)
{
    __shared__ __align__(16) float As[32][260];
    __shared__ __align__(16) float Bs[32][68];

    const float* A = (mode == 0) ? A_in : g_ao;
    int tid = threadIdx.x;
    int tn = tid & 15, tm = tid >> 4;
    size_t m0 = (size_t)blockIdx.x * 256;
    int n0 = blockIdx.y * 64;

    ull acc[8][4];
#pragma unroll
    for (int i = 0; i < 8; ++i)
#pragma unroll
        for (int j = 0; j < 4; ++j) acc[i][j] = 0ULL;

    for (int kt = 0; kt < 6; ++kt) {
        int k0 = kt * 32;
#pragma unroll
        for (int it = 0; it < 8; ++it) {
            int fid = tid + it * 256;
            int ml = fid >> 3, kc = fid & 7;
            float4 v = *(const float4*)(A + (m0 + ml) * DIMM + k0 + kc * 4);
            As[kc * 4 + 0][ml] = v.x;
            As[kc * 4 + 1][ml] = v.y;
            As[kc * 4 + 2][ml] = v.z;
            As[kc * 4 + 3][ml] = v.w;
        }
#pragma unroll
        for (int it = 0; it < 2; ++it) {
            int fid = tid + it * 256;
            int nl = fid >> 3, kc = fid & 7;
            float4 v = *(const float4*)(W + (size_t)(n0 + nl) * DIMM + k0 + kc * 4);
            Bs[kc * 4 + 0][nl] = v.x;
            Bs[kc * 4 + 1][nl] = v.y;
            Bs[kc * 4 + 2][nl] = v.z;
            Bs[kc * 4 + 3][nl] = v.w;
        }
        __syncthreads();
#pragma unroll
        for (int k = 0; k < 32; ++k) {
            const ulonglong2* ap = (const ulonglong2*)&As[k][tm * 16];
            ull a2[8];
#pragma unroll
            for (int c = 0; c < 4; ++c) {
                ulonglong2 t = ap[c];
                a2[2 * c] = t.x; a2[2 * c + 1] = t.y;
            }
            float4 bv = *(const float4*)&Bs[k][tn * 4];
            ull b0 = dup2(bv.x), b1 = dup2(bv.y), b2 = dup2(bv.z), b3 = dup2(bv.w);
#pragma unroll
            for (int i = 0; i < 8; ++i) {
                acc[i][0] = fma2(a2[i], b0, acc[i][0]);
                acc[i][1] = fma2(a2[i], b1, acc[i][1]);
                acc[i][2] = fma2(a2[i], b2, acc[i][2]);
                acc[i][3] = fma2(a2[i], b3, acc[i][3]);
            }
        }
        __syncthreads();
    }

    /* epilogue */
    int c0 = n0 + tn * 4;
    int which = c0 / DIMM;
    int rem = c0 - which * DIMM;
    int hh = rem >> 5;
    int d0 = rem & 31;
    float qs = (which == 0) ? QS_LOG2E : 1.0f;
    float* dst = (which == 0) ? g_q : ((which == 1) ? g_k : g_v);
    float bvs[4];
#pragma unroll
    for (int j = 0; j < 4; ++j) bvs[j] = bias[c0 + j];

#pragma unroll
    for (int i = 0; i < 8; ++i) {
        size_t mA = m0 + tm * 16 + 2 * i;
        if (mode == 1) {
#pragma unroll
            for (int j = 0; j < 4; ++j) {
                float2 v = u2f(acc[i][j]);
                outp[mA * DIMM + c0 + j] = v.x + bvs[j];
                outp[(mA + 1) * DIMM + c0 + j] = v.y + bvs[j];
            }
        } else {
            int b1 = (int)(mA / N_TOK), n1 = (int)(mA - (size_t)b1 * N_TOK);
            size_t r2 = mA + 1;
            int b2 = (int)(r2 / N_TOK), n2 = (int)(r2 - (size_t)b2 * N_TOK);
            size_t o1 = (((size_t)b1 * NH + hh) * N_TOK + n1) * HD + d0;
            size_t o2 = (((size_t)b2 * NH + hh) * N_TOK + n2) * HD + d0;
#pragma unroll
            for (int j = 0; j < 4; ++j) {
                float2 v = u2f(acc[i][j]);
                dst[o1 + j] = (v.x + bvs[j]) * qs;
                dst[o2 + j] = (v.y + bvs[j]) * qs;
            }
        }
    }
}

/* ------------------------------------------------------------------ */
/* Attention v5: software-pipelined j-loop + L2-reuse CTA ordering.    */
/* One CTA per (b,h); K,V in smem padded to 345 rows (rows 343,344=0). */
/* 176 threads; thread t owns query rows t and t+176.                  */
/* blockIdx remapped so the 4 CTAs sharing a g_bm (h,w)-slice run      */
/* adjacently -> DRAM traffic /4, rest L2 hits.                        */
/* Pipeline: iteration j computes dot(j+1) (independent FMA stream)    */
/* while finishing softmax(j) + PV(j) -> hides the serial chain.       */
/* ------------------------------------------------------------------ */
__global__ __launch_bounds__(176, 2) void attn_kernel() {
    extern __shared__ float sm[];
    float* ks = sm;
    float* vs = sm + N_EXT * HD;

    int tid = threadIdx.x;
    int bh = blockIdx.x;
    int hw  = bh >> 2;          /* h*64+w : 0..383 */
    int img = bh & 3;
    int hh = hw >> 6;
    int w  = hw & 63;
    int bb = img * NWIN + w;

    size_t base = ((size_t)bb * NH + hh) * N_TOK * HD;

    { /* stage K and V + two zero pad rows, coalesced */
        const float4* ksrc = (const float4*)(g_k + base);
        const float4* vsrc = (const float4*)(g_v + base);
        float4* kdst = (float4*)ks;
        float4* vdst = (float4*)vs;
        const float4 z = make_float4(0.f, 0.f, 0.f, 0.f);
        for (int i = tid; i < N_EXT * HD / 4; i += 176) {
            bool in = (i < N_TOK * HD / 4);
            kdst[i] = in ? ksrc[i] : z;
            vdst[i] = in ? vsrc[i] : z;
        }
    }
    __syncthreads();

    int rA = tid;                       /* always < 343 */
    bool hasB = (tid < N_TOK - 176);    /* tid < 167 */
    int rB = hasB ? tid + 176 : tid;    /* alias A when inactive */

    const float* pbm = g_bm + (size_t)hw * (N_PAD * N_TOK);
    const float* pA = pbm + rA;
    const float* pB = pbm + rB;

    ull qA[16], qB[16], oA[16], oB[16];
    {
        const ulonglong2* qa = (const ulonglong2*)(g_q + base + (size_t)rA * HD);
        const ulonglong2* qb = (const ulonglong2*)(g_q + base + (size_t)rB * HD);
#pragma unroll
        for (int c = 0; c < 8; ++c) {
            ulonglong2 ta = qa[c], tb = qb[c];
            qA[2 * c] = ta.x; qA[2 * c + 1] = ta.y;
            qB[2 * c] = tb.x; qB[2 * c + 1] = tb.y;
        }
    }
#pragma unroll
    for (int c = 0; c < 16; ++c) { oA[c] = 0ULL; oB[c] = 0ULL; }
    float lA = 0.f, lB = 0.f;

    /* rolling register prefetch of fused bias+mask, depth 4..8 keys */
    float curA[4], curB[4];
#pragma unroll
    for (int t = 0; t < 4; ++t) {
        curA[t] = __ldg(pA + t * N_TOK);
        curB[t] = __ldg(pB + t * N_TOK);
    }
    pA += 4 * N_TOK;
    pB += 4 * N_TOK;

    /* prologue: dot(0) */
    const float* kp = ks;
    const float* vp = vs;
    ull dpA0 = 0, dpA1 = 0, dpB0 = 0, dpB1 = 0;
    {
        const ulonglong2* kr = (const ulonglong2*)kp;
#pragma unroll
        for (int c = 0; c < 8; ++c) {
            ulonglong2 t = kr[c];
            dpA0 = fma2(qA[2 * c],     t.x, dpA0);
            dpA1 = fma2(qA[2 * c + 1], t.y, dpA1);
            dpB0 = fma2(qB[2 * c],     t.x, dpB0);
            dpB1 = fma2(qB[2 * c + 1], t.y, dpB1);
        }
    }
    kp += HD;   /* points at K(1) */

    for (int o = 0; o < N_PAD / 4; ++o) {          /* 86 iterations */
        float nxtA[4], nxtB[4];
#pragma unroll
        for (int t = 0; t < 4; ++t) {
            nxtA[t] = __ldg(pA + t * N_TOK);
            nxtB[t] = __ldg(pB + t * N_TOK);
        }
        pA += 4 * N_TOK;
        pB += 4 * N_TOK;

#pragma unroll
        for (int jj = 0; jj < 4; ++jj) {
            /* --- next dot: dot(j+1), independent of softmax/PV below --- */
            const ulonglong2* kr = (const ulonglong2*)kp;
            ull nA0 = 0, nA1 = 0, nB0 = 0, nB1 = 0;
#pragma unroll
            for (int c = 0; c < 8; ++c) {
                ulonglong2 t = kr[c];
                nA0 = fma2(qA[2 * c],     t.x, nA0);
                nA1 = fma2(qA[2 * c + 1], t.y, nA1);
                nB0 = fma2(qB[2 * c],     t.x, nB0);
                nB1 = fma2(qB[2 * c + 1], t.y, nB1);
            }

            /* --- softmax of dot(j) --- */
            float sA = hsum2(dpA0, dpA1) + curA[jj];
            float sB = hsum2(dpB0, dpB1) + curB[jj];
            float pAx = ex2f(sA);
            float pBx = ex2f(sB);
            lA += pAx; lB += pBx;
            ull pA2 = dup2(pAx), pB2 = dup2(pBx);

            /* --- PV with V(j) --- */
            const ulonglong2* vr = (const ulonglong2*)vp;
#pragma unroll
            for (int c = 0; c < 8; ++c) {
                ulonglong2 t = vr[c];
                oA[2 * c]     = fma2(pA2, t.x, oA[2 * c]);
                oA[2 * c + 1] = fma2(pA2, t.y, oA[2 * c + 1]);
                oB[2 * c]     = fma2(pB2, t.x, oB[2 * c]);
                oB[2 * c + 1] = fma2(pB2, t.y, oB[2 * c + 1]);
            }

            dpA0 = nA0; dpA1 = nA1; dpB0 = nB0; dpB1 = nB1;
            kp += HD; vp += HD;
        }
#pragma unroll
        for (int t = 0; t < 4; ++t) { curA[t] = nxtA[t]; curB[t] = nxtB[t]; }
    }

    {
        float inv = 1.0f / lA;
        float4* dp = (float4*)(g_ao + ((size_t)bb * N_TOK + rA) * DIMM + hh * HD);
#pragma unroll
        for (int c = 0; c < 8; ++c) {
            float2 p0 = u2f(oA[2 * c]), p1 = u2f(oA[2 * c + 1]);
            dp[c] = make_float4(p0.x * inv, p0.y * inv, p1.x * inv, p1.y * inv);
        }
    }
    if (hasB) {
        float inv = 1.0f / lB;
        float4* dp = (float4*)(g_ao + ((size_t)bb * N_TOK + rB) * DIMM + hh * HD);
#pragma unroll
        for (int c = 0; c < 8; ++c) {
            float2 p0 = u2f(oB[2 * c]), p1 = u2f(oB[2 * c + 1]);
            dp[c] = make_float4(p0.x * inv, p0.y * inv, p1.x * inv, p1.y * inv);
        }
    }
}

/* ------------------------------------------------------------------ */
extern "C" void kernel_launch(void* const* d_in, const int* in_sizes, int n_in,
                              void* d_out, int out_size) {
    const float* x      = (const float*)d_in[0];
    const float* mask   = (const float*)d_in[1];
    const float* qkv_w  = (const float*)d_in[2];
    const float* qkv_b  = (const float*)d_in[3];
    const float* rpb    = (const float*)d_in[4];
    const float* proj_w = (const float*)d_in[5];
    const float* proj_b = (const float*)d_in[6];
    float* out = (float*)d_out;

    const int smem_attn = N_EXT * 2 * HD * sizeof(float);  /* 88320 B */
    cudaFuncSetAttribute(attn_kernel,
                         cudaFuncAttributeMaxDynamicSharedMemorySize, smem_attn);

    transpose_mask_kernel<<<dim3(11, 11, NWIN), dim3(32, 8)>>>(mask);
    combine_bm_kernel<<<dim3(N_PAD, NWIN), N_TOK>>>(rpb);
    gemm_kernel<<<dim3(M_ROWS / 256, 9), 256>>>(x, qkv_w, qkv_b, nullptr, 0);
    attn_kernel<<<BATCH * NH, 176, smem_attn>>>();
    gemm_kernel<<<dim3(M_ROWS / 256, 3), 256>>>(nullptr, proj_w, proj_b, out, 1);
}

// round 15
// speedup vs baseline: 1.0344x; 1.0082x over previous
#include <cuda_runtime.h>
#include <cstdint>

typedef unsigned long long ull;

#define N_TOK 343
#define N_PAD 344                       /* j=343 = dummy key (-inf bias) */
#define DIMM  192
#define NH    6
#define HD    32
#define BATCH 256
#define NWIN  64
#define M_ROWS (BATCH * N_TOK)          /* 87808 = 343 * 256 */
#define QS_LOG2E (0.17677669529663687f * 1.4426950408889634f)
#define LOG2E    1.4426950408889634f

/* ------------------------------------------------------------------ */
/* Device scratch                                                      */
/* ------------------------------------------------------------------ */
__device__ float g_q[(size_t)BATCH * NH * N_TOK * HD];
__device__ float g_k[(size_t)BATCH * NH * N_TOK * HD];
__device__ float g_v[(size_t)BATCH * NH * N_TOK * HD];
__device__ float g_ao[(size_t)M_ROWS * DIMM];
__device__ float g_maskT[(size_t)NWIN * N_TOK * N_TOK];   /* [w][j][i] */
/* fused (bias+mask)*log2e, [h*64+w][j(344)][i(343)]; row j=343 = -inf */
__device__ float g_bm[(size_t)NH * NWIN * N_PAD * N_TOK + 2048];

/* ------------------------------------------------------------------ */
/* helpers                                                             */
/* ------------------------------------------------------------------ */
__device__ __forceinline__ ull fma2(ull a, ull b, ull c) {
    ull d;
    asm("fma.rn.f32x2 %0, %1, %2, %3;" : "=l"(d) : "l"(a), "l"(b), "l"(c));
    return d;
}
__device__ __forceinline__ ull add2(ull a, ull b) {
    ull d;
    asm("add.rn.f32x2 %0, %1, %2;" : "=l"(d) : "l"(a), "l"(b));
    return d;
}
__device__ __forceinline__ ull dup2(float x) {
    ull r;
    asm("mov.b64 %0, {%1, %1};" : "=l"(r) : "f"(x));
    return r;
}
__device__ __forceinline__ float2 u2f(ull x) {
    float2 r;
    asm("mov.b64 {%0, %1}, %2;" : "=f"(r.x), "=f"(r.y) : "l"(x));
    return r;
}
__device__ __forceinline__ float hsum2(ull a, ull b) {
    float2 f = u2f(add2(a, b));
    return f.x + f.y;
}
__device__ __forceinline__ float ex2f(float x) {
    float y;
    asm("ex2.approx.f32 %0, %1;" : "=f"(y) : "f"(x));
    return y;
}
__device__ __forceinline__ uint32_t tf32_hi(float f) {
    uint32_t r;
    asm("cvt.rna.tf32.f32 %0, %1;" : "=r"(r) : "f"(f));
    return r;
}
__device__ __forceinline__ void tf32_split(float f, uint32_t& hi, uint32_t& lo) {
    hi = tf32_hi(f);
    float rem = f - __uint_as_float(hi);
    lo = tf32_hi(rem);
}
__device__ __forceinline__ void mma1688(float* c,
    uint32_t a0, uint32_t a1, uint32_t a2, uint32_t a3,
    uint32_t b0, uint32_t b1)
{
    asm volatile(
        "mma.sync.aligned.m16n8k8.row.col.f32.tf32.tf32.f32 "
        "{%0,%1,%2,%3}, {%4,%5,%6,%7}, {%8,%9}, {%0,%1,%2,%3};"
        : "+f"(c[0]), "+f"(c[1]), "+f"(c[2]), "+f"(c[3])
        : "r"(a0), "r"(a1), "r"(a2), "r"(a3), "r"(b0), "r"(b1));
}

/* ------------------------------------------------------------------ */
/* Kernel 0a: transpose mask -> [w][j][i]                              */
/* ------------------------------------------------------------------ */
__global__ void transpose_mask_kernel(const float* __restrict__ mask) {
    __shared__ float t[32][33];
    int w = blockIdx.z;
    int j0 = blockIdx.x * 32, i0 = blockIdx.y * 32;
    int tx = threadIdx.x, ty = threadIdx.y;
#pragma unroll
    for (int k = 0; k < 32; k += 8) {
        int i = i0 + ty + k, j = j0 + tx;
        if (i < N_TOK && j < N_TOK)
            t[ty + k][tx] = mask[((size_t)w * N_TOK + i) * N_TOK + j];
    }
    __syncthreads();
#pragma unroll
    for (int k = 0; k < 32; k += 8) {
        int j = j0 + ty + k, i = i0 + tx;
        if (i < N_TOK && j < N_TOK)
            g_maskT[((size_t)w * N_TOK + j) * N_TOK + i] = t[tx][ty + k];
    }
}

/* ------------------------------------------------------------------ */
/* Kernel 0b: fuse (bias + mask)*log2e into g_bm[h*64+w][j][i]         */
/* ------------------------------------------------------------------ */
__global__ void combine_bm_kernel(const float* __restrict__ table) {
    int i = threadIdx.x;
    int j = blockIdx.x;
    int w = blockIdx.y;

    if (j == N_TOK) {
        float ninf = __int_as_float(0xff800000);
#pragma unroll
        for (int h = 0; h < NH; ++h)
            g_bm[(((size_t)h * NWIN + w) * N_PAD + N_TOK) * N_TOK + i] = ninf;
        return;
    }
    int di = i / 49, hi = (i / 7) % 7, wi = i % 7;
    int dj = j / 49, hj = (j / 7) % 7, wj = j % 7;
    int idx = (di - dj + 6) * 169 + (hi - hj + 6) * 13 + (wi - wj + 6);
    float m = g_maskT[((size_t)w * N_TOK + j) * N_TOK + i];
#pragma unroll
    for (int h = 0; h < NH; ++h) {
        float b = __ldg(table + idx * NH + h);
        g_bm[(((size_t)h * NWIN + w) * N_PAD + j) * N_TOK + i] = (b + m) * LOG2E;
    }
}

/* ------------------------------------------------------------------ */
/* Tensor-core GEMM (3xTF32): Y[M,NN] = A[M,192] @ W[NN,192]^T + bias  */
/*   BM=128, BN=64, BK=32; 256 thr = 8 warps, warp tile 32x32          */
/*   (2x4 m16n8k8 frags, hi/lo split -> fp32-level accuracy)           */
/*   mode 0: scatter q/k/v (+QS_LOG2E on q), mode 1: write outp        */
/* ------------------------------------------------------------------ */
__global__ __launch_bounds__(256, 2) void gemm_tc_kernel(
    const float* __restrict__ A_in, const float* __restrict__ W,
    const float* __restrict__ bias, float* __restrict__ outp, int mode)
{
    __shared__ __align__(16) float As[32][136];   /* [k][m], pad->conflict-free */
    __shared__ __align__(16) float Bs[32][72];    /* [k][n] */

    const float* A = (mode == 0) ? A_in : g_ao;
    int tid = threadIdx.x;
    int lane = tid & 31;
    int warp = tid >> 5;
    int g = lane >> 2, t = lane & 3;
    int wm = warp >> 1, wn = warp & 1;
    size_t m0 = (size_t)blockIdx.x * 128;
    int n0 = blockIdx.y * 64;

    float acc[2][4][4];
#pragma unroll
    for (int a = 0; a < 2; ++a)
#pragma unroll
        for (int b = 0; b < 4; ++b)
#pragma unroll
            for (int c = 0; c < 4; ++c) acc[a][b][c] = 0.f;

    for (int kt = 0; kt < 6; ++kt) {
        int k0 = kt * 32;
#pragma unroll
        for (int it = 0; it < 4; ++it) {
            int fid = tid + it * 256;
            int ml = fid >> 3, kc = fid & 7;
            float4 v = *(const float4*)(A + (m0 + ml) * DIMM + k0 + kc * 4);
            As[kc * 4 + 0][ml] = v.x;
            As[kc * 4 + 1][ml] = v.y;
            As[kc * 4 + 2][ml] = v.z;
            As[kc * 4 + 3][ml] = v.w;
        }
#pragma unroll
        for (int it = 0; it < 2; ++it) {
            int fid = tid + it * 256;
            int nl = fid >> 3, kc = fid & 7;
            float4 v = *(const float4*)(W + (size_t)(n0 + nl) * DIMM + k0 + kc * 4);
            Bs[kc * 4 + 0][nl] = v.x;
            Bs[kc * 4 + 1][nl] = v.y;
            Bs[kc * 4 + 2][nl] = v.z;
            Bs[kc * 4 + 3][nl] = v.w;
        }
        __syncthreads();

#pragma unroll
        for (int kc = 0; kc < 4; ++kc) {
            int kr = kc * 8 + t;
            uint32_t Ah[2][4], Al[2][4];
#pragma unroll
            for (int mt = 0; mt < 2; ++mt) {
                int mb = wm * 32 + mt * 16 + g;
                float f0 = As[kr][mb];
                float f1 = As[kr][mb + 8];
                float f2 = As[kr + 4][mb];
                float f3 = As[kr + 4][mb + 8];
                tf32_split(f0, Ah[mt][0], Al[mt][0]);
                tf32_split(f1, Ah[mt][1], Al[mt][1]);
                tf32_split(f2, Ah[mt][2], Al[mt][2]);
                tf32_split(f3, Ah[mt][3], Al[mt][3]);
            }
            uint32_t Bh[4][2], Bl[4][2];
#pragma unroll
            for (int nt = 0; nt < 4; ++nt) {
                int nb = wn * 32 + nt * 8 + g;
                float f0 = Bs[kr][nb];
                float f1 = Bs[kr + 4][nb];
                tf32_split(f0, Bh[nt][0], Bl[nt][0]);
                tf32_split(f1, Bh[nt][1], Bl[nt][1]);
            }
#pragma unroll
            for (int mt = 0; mt < 2; ++mt)
#pragma unroll
                for (int nt = 0; nt < 4; ++nt) {
                    mma1688(acc[mt][nt], Ah[mt][0], Ah[mt][1], Ah[mt][2], Ah[mt][3],
                            Bh[nt][0], Bh[nt][1]);
                    mma1688(acc[mt][nt], Ah[mt][0], Ah[mt][1], Ah[mt][2], Ah[mt][3],
                            Bl[nt][0], Bl[nt][1]);
                    mma1688(acc[mt][nt], Al[mt][0], Al[mt][1], Al[mt][2], Al[mt][3],
                            Bh[nt][0], Bh[nt][1]);
                }
        }
        __syncthreads();
    }

    /* epilogue */
#pragma unroll
    for (int mt = 0; mt < 2; ++mt) {
        int r0 = (int)m0 + wm * 32 + mt * 16 + g;
        int r1 = r0 + 8;
        int ib0 = r0 / N_TOK, in0 = r0 - ib0 * N_TOK;
        int ib1 = r1 / N_TOK, in1 = r1 - ib1 * N_TOK;
#pragma unroll
        for (int nt = 0; nt < 4; ++nt) {
            int c = n0 + wn * 32 + nt * 8 + 2 * t;
            float bv0 = bias[c], bv1 = bias[c + 1];
            if (mode == 1) {
                float2 v0 = make_float2(acc[mt][nt][0] + bv0, acc[mt][nt][1] + bv1);
                float2 v1 = make_float2(acc[mt][nt][2] + bv0, acc[mt][nt][3] + bv1);
                *(float2*)(outp + (size_t)r0 * DIMM + c) = v0;
                *(float2*)(outp + (size_t)r1 * DIMM + c) = v1;
            } else {
                int which = c / DIMM;
                int rem = c - which * DIMM;
                int hh = rem >> 5;
                int d0 = rem & 31;
                float qs = (which == 0) ? QS_LOG2E : 1.0f;
                float* dst = (which == 0) ? g_q : ((which == 1) ? g_k : g_v);
                size_t o0 = (((size_t)ib0 * NH + hh) * N_TOK + in0) * HD + d0;
                size_t o1 = (((size_t)ib1 * NH + hh) * N_TOK + in1) * HD + d0;
                float2 v0 = make_float2((acc[mt][nt][0] + bv0) * qs,
                                        (acc[mt][nt][1] + bv1) * qs);
                float2 v1 = make_float2((acc[mt][nt][2] + bv0) * qs,
                                        (acc[mt][nt][3] + bv1) * qs);
                *(float2*)(dst + o0) = v0;
                *(float2*)(dst + o1) = v1;
            }
        }
    }
}

/* ------------------------------------------------------------------ */
/* Attention (R12 loop + L2-reuse CTA remap): one CTA per (b,h).       */
/* K,V staged in smem w/ zero pad row (88.1KB). 176 threads; thread t  */
/* owns query rows t and t+176. 86 uniform iterations of 4 keys; fused */
/* bias+mask register-prefetched 4..8 keys ahead; softmax = ex2.       */
/* blockIdx remapped so 4 CTAs sharing a g_bm (h,w)-slice run          */
/* adjacently -> slice loads DRAM once, 3 L2 hits.                     */
/* ------------------------------------------------------------------ */
__global__ __launch_bounds__(176, 2) void attn_kernel() {
    extern __shared__ float sm[];
    float* ks = sm;
    float* vs = sm + N_PAD * HD;

    int tid = threadIdx.x;
    int bh = blockIdx.x;
    int hw  = bh >> 2;          /* h*64+w : 0..383 */
    int img = bh & 3;
    int hh = hw >> 6;
    int w  = hw & 63;
    int bb = img * NWIN + w;

    size_t base = ((size_t)bb * NH + hh) * N_TOK * HD;

    { /* stage K and V + zero pad row, coalesced */
        const float4* ksrc = (const float4*)(g_k + base);
        const float4* vsrc = (const float4*)(g_v + base);
        float4* kdst = (float4*)ks;
        float4* vdst = (float4*)vs;
        const float4 z = make_float4(0.f, 0.f, 0.f, 0.f);
        for (int i = tid; i < N_PAD * HD / 4; i += 176) {
            bool in = (i < N_TOK * HD / 4);
            kdst[i] = in ? ksrc[i] : z;
            vdst[i] = in ? vsrc[i] : z;
        }
    }
    __syncthreads();

    int rA = tid;
    bool hasB = (tid < N_TOK - 176);
    int rB = hasB ? tid + 176 : tid;

    const float* pbm = g_bm + (size_t)hw * (N_PAD * N_TOK);
    const float* pA = pbm + rA;
    const float* pB = pbm + rB;

    ull qA[16], qB[16], oA[16], oB[16];
    {
        const ulonglong2* qa = (const ulonglong2*)(g_q + base + (size_t)rA * HD);
        const ulonglong2* qb = (const ulonglong2*)(g_q + base + (size_t)rB * HD);
#pragma unroll
        for (int c = 0; c < 8; ++c) {
            ulonglong2 ta = qa[c], tb = qb[c];
            qA[2 * c] = ta.x; qA[2 * c + 1] = ta.y;
            qB[2 * c] = tb.x; qB[2 * c + 1] = tb.y;
        }
    }
#pragma unroll
    for (int c = 0; c < 16; ++c) { oA[c] = 0ULL; oB[c] = 0ULL; }
    float lA = 0.f, lB = 0.f;

    float curA[4], curB[4], nxtA[4], nxtB[4];
#pragma unroll
    for (int t = 0; t < 4; ++t) {
        curA[t] = __ldg(pA + t * N_TOK);
        curB[t] = __ldg(pB + t * N_TOK);
    }

    int koff = 0;
    for (int o = 0; o < N_PAD / 4; ++o) {          /* 86 iterations */
        int jpf = (o * 4 + 4) * N_TOK;
#pragma unroll
        for (int t = 0; t < 4; ++t) {
            nxtA[t] = __ldg(pA + jpf + t * N_TOK);
            nxtB[t] = __ldg(pB + jpf + t * N_TOK);
        }
#pragma unroll
        for (int jj = 0; jj < 4; ++jj) {
            const ulonglong2* kr = (const ulonglong2*)(ks + koff);
            ull dA0 = 0, dA1 = 0, dB0 = 0, dB1 = 0;
#pragma unroll
            for (int c = 0; c < 8; ++c) {
                ulonglong2 t = kr[c];
                dA0 = fma2(qA[2 * c],     t.x, dA0);
                dA1 = fma2(qA[2 * c + 1], t.y, dA1);
                dB0 = fma2(qB[2 * c],     t.x, dB0);
                dB1 = fma2(qB[2 * c + 1], t.y, dB1);
            }
            float sA = hsum2(dA0, dA1) + curA[jj];
            float sB = hsum2(dB0, dB1) + curB[jj];
            float pAx = ex2f(sA);
            float pBx = ex2f(sB);
            lA += pAx; lB += pBx;
            ull pA2 = dup2(pAx), pB2 = dup2(pBx);

            const ulonglong2* vr = (const ulonglong2*)(vs + koff);
#pragma unroll
            for (int c = 0; c < 8; ++c) {
                ulonglong2 t = vr[c];
                oA[2 * c]     = fma2(pA2, t.x, oA[2 * c]);
                oA[2 * c + 1] = fma2(pA2, t.y, oA[2 * c + 1]);
                oB[2 * c]     = fma2(pB2, t.x, oB[2 * c]);
                oB[2 * c + 1] = fma2(pB2, t.y, oB[2 * c + 1]);
            }
            koff += HD;
        }
#pragma unroll
        for (int t = 0; t < 4; ++t) { curA[t] = nxtA[t]; curB[t] = nxtB[t]; }
    }

    {
        float inv = 1.0f / lA;
        float4* dp = (float4*)(g_ao + ((size_t)bb * N_TOK + rA) * DIMM + hh * HD);
#pragma unroll
        for (int c = 0; c < 8; ++c) {
            float2 p0 = u2f(oA[2 * c]), p1 = u2f(oA[2 * c + 1]);
            dp[c] = make_float4(p0.x * inv, p0.y * inv, p1.x * inv, p1.y * inv);
        }
    }
    if (hasB) {
        float inv = 1.0f / lB;
        float4* dp = (float4*)(g_ao + ((size_t)bb * N_TOK + rB) * DIMM + hh * HD);
#pragma unroll
        for (int c = 0; c < 8; ++c) {
            float2 p0 = u2f(oB[2 * c]), p1 = u2f(oB[2 * c + 1]);
            dp[c] = make_float4(p0.x * inv, p0.y * inv, p1.x * inv, p1.y * inv);
        }
    }
}

/* ------------------------------------------------------------------ */
extern "C" void kernel_launch(void* const* d_in, const int* in_sizes, int n_in,
                              void* d_out, int out_size) {
    const float* x      = (const float*)d_in[0];
    const float* mask   = (const float*)d_in[1];
    const float* qkv_w  = (const float*)d_in[2];
    const float* qkv_b  = (const float*)d_in[3];
    const float* rpb    = (const float*)d_in[4];
    const float* proj_w = (const float*)d_in[5];
    const float* proj_b = (const float*)d_in[6];
    float* out = (float*)d_out;

    const int smem_attn = N_PAD * 2 * HD * sizeof(float);  /* 88064 B */
    cudaFuncSetAttribute(attn_kernel,
                         cudaFuncAttributeMaxDynamicSharedMemorySize, smem_attn);

    transpose_mask_kernel<<<dim3(11, 11, NWIN), dim3(32, 8)>>>(mask);
    combine_bm_kernel<<<dim3(N_PAD, NWIN), N_TOK>>>(rpb);
    gemm_tc_kernel<<<dim3(M_ROWS / 128, 9), 256>>>(x, qkv_w, qkv_b, nullptr, 0);
    attn_kernel<<<BATCH * NH, 176, smem_attn>>>();
    gemm_tc_kernel<<<dim3(M_ROWS / 128, 3), 256>>>(nullptr, proj_w, proj_b, out, 1);
}

// round 17
// speedup vs baseline: 1.4393x; 1.3913x over previous
#include <cuda_runtime.h>
#include <cuda_bf16.h>
#include <cstdint>

typedef unsigned int uint;

#define N_TOK 343
#define N_JPAD 352                      /* padded key dim for mma (16x22) */
#define DIMM  192
#define NH    6
#define HD    32
#define BATCH 256
#define NWIN  64
#define M_ROWS (BATCH * N_TOK)          /* 87808 = 343 * 256 */
#define QS_LOG2E (0.17677669529663687f * 1.4426950408889634f)
#define LOG2E    1.4426950408889634f

#define KP 20                           /* K smem pitch (uints per key row)  */
#define VP 180                          /* V^T smem pitch (uints per d row)  */

/* ------------------------------------------------------------------ */
/* Device scratch                                                      */
/* ------------------------------------------------------------------ */
__device__ float g_q[(size_t)BATCH * NH * N_TOK * HD];
__device__ float g_k[(size_t)BATCH * NH * N_TOK * HD];
__device__ float g_v[(size_t)BATCH * NH * N_TOK * HD];
__device__ float g_ao[(size_t)M_ROWS * DIMM];
__device__ float g_maskT[(size_t)NWIN * N_TOK * N_TOK];   /* [w][j][i] */
/* fused (bias+mask)*log2e, [h*64+w][j(352)][i(343)]; rows j>=343 = -inf */
__device__ float g_bm[(size_t)NH * NWIN * N_JPAD * N_TOK + 16384];

/* ------------------------------------------------------------------ */
/* helpers                                                             */
/* ------------------------------------------------------------------ */
__device__ __forceinline__ float ex2f(float x) {
    float y;
    asm("ex2.approx.f32 %0, %1;" : "=f"(y) : "f"(x));
    return y;
}
/* pack {lo=x, hi=y} as bf16x2 and produce the compensation (lo) pair   */
__device__ __forceinline__ void bfsplit2(float x, float y, uint& h, uint& l) {
    asm("cvt.rn.bf16x2.f32 %0, %1, %2;" : "=r"(h) : "f"(y), "f"(x));
    float rx = x - __uint_as_float(h << 16);
    float ry = y - __uint_as_float(h & 0xffff0000u);
    asm("cvt.rn.bf16x2.f32 %0, %1, %2;" : "=r"(l) : "f"(ry), "f"(rx));
}
__device__ __forceinline__ void mma_bf(float* c,
    uint a0, uint a1, uint a2, uint a3, uint b0, uint b1)
{
    asm volatile(
        "mma.sync.aligned.m16n8k16.row.col.f32.bf16.bf16.f32 "
        "{%0,%1,%2,%3}, {%4,%5,%6,%7}, {%8,%9}, {%0,%1,%2,%3};"
        : "+f"(c[0]), "+f"(c[1]), "+f"(c[2]), "+f"(c[3])
        : "r"(a0), "r"(a1), "r"(a2), "r"(a3), "r"(b0), "r"(b1));
}
__device__ __forceinline__ uint tf32_hi(float f) {
    uint r;
    asm("cvt.rna.tf32.f32 %0, %1;" : "=r"(r) : "f"(f));
    return r;
}
__device__ __forceinline__ void tf32_split(float f, uint& hi, uint& lo) {
    hi = tf32_hi(f);
    float rem = f - __uint_as_float(hi);
    lo = tf32_hi(rem);
}
__device__ __forceinline__ void mma1688(float* c,
    uint a0, uint a1, uint a2, uint a3, uint b0, uint b1)
{
    asm volatile(
        "mma.sync.aligned.m16n8k8.row.col.f32.tf32.tf32.f32 "
        "{%0,%1,%2,%3}, {%4,%5,%6,%7}, {%8,%9}, {%0,%1,%2,%3};"
        : "+f"(c[0]), "+f"(c[1]), "+f"(c[2]), "+f"(c[3])
        : "r"(a0), "r"(a1), "r"(a2), "r"(a3), "r"(b0), "r"(b1));
}

/* ------------------------------------------------------------------ */
/* Kernel 0a: transpose mask -> [w][j][i]                              */
/* ------------------------------------------------------------------ */
__global__ void transpose_mask_kernel(const float* __restrict__ mask) {
    __shared__ float t[32][33];
    int w = blockIdx.z;
    int j0 = blockIdx.x * 32, i0 = blockIdx.y * 32;
    int tx = threadIdx.x, ty = threadIdx.y;
#pragma unroll
    for (int k = 0; k < 32; k += 8) {
        int i = i0 + ty + k, j = j0 + tx;
        if (i < N_TOK && j < N_TOK)
            t[ty + k][tx] = mask[((size_t)w * N_TOK + i) * N_TOK + j];
    }
    __syncthreads();
#pragma unroll
    for (int k = 0; k < 32; k += 8) {
        int j = j0 + ty + k, i = i0 + tx;
        if (i < N_TOK && j < N_TOK)
            g_maskT[((size_t)w * N_TOK + j) * N_TOK + i] = t[tx][ty + k];
    }
}

/* ------------------------------------------------------------------ */
/* Kernel 0b: fuse (bias + mask)*log2e into g_bm[h*64+w][j][i]         */
/* rows j in [343,352) = -inf                                          */
/* ------------------------------------------------------------------ */
__global__ void combine_bm_kernel(const float* __restrict__ table) {
    int i = threadIdx.x;
    int j = blockIdx.x;
    int w = blockIdx.y;

    if (j >= N_TOK) {
        float ninf = __int_as_float(0xff800000);
#pragma unroll
        for (int h = 0; h < NH; ++h)
            g_bm[(((size_t)h * NWIN + w) * N_JPAD + j) * N_TOK + i] = ninf;
        return;
    }
    int di = i / 49, hi = (i / 7) % 7, wi = i % 7;
    int dj = j / 49, hj = (j / 7) % 7, wj = j % 7;
    int idx = (di - dj + 6) * 169 + (hi - hj + 6) * 13 + (wi - wj + 6);
    float m = g_maskT[((size_t)w * N_TOK + j) * N_TOK + i];
#pragma unroll
    for (int h = 0; h < NH; ++h) {
        float b = __ldg(table + idx * NH + h);
        g_bm[(((size_t)h * NWIN + w) * N_JPAD + j) * N_TOK + i] = (b + m) * LOG2E;
    }
}

/* ------------------------------------------------------------------ */
/* Tensor-core GEMM (3xTF32) — unchanged from R15 (passing, 5e-6)      */
/* ------------------------------------------------------------------ */
__global__ __launch_bounds__(256, 2) void gemm_tc_kernel(
    const float* __restrict__ A_in, const float* __restrict__ W,
    const float* __restrict__ bias, float* __restrict__ outp, int mode)
{
    __shared__ __align__(16) float As[32][136];
    __shared__ __align__(16) float Bs[32][72];

    const float* A = (mode == 0) ? A_in : g_ao;
    int tid = threadIdx.x;
    int lane = tid & 31;
    int warp = tid >> 5;
    int g = lane >> 2, t = lane & 3;
    int wm = warp >> 1, wn = warp & 1;
    size_t m0 = (size_t)blockIdx.x * 128;
    int n0 = blockIdx.y * 64;

    float acc[2][4][4];
#pragma unroll
    for (int a = 0; a < 2; ++a)
#pragma unroll
        for (int b = 0; b < 4; ++b)
#pragma unroll
            for (int c = 0; c < 4; ++c) acc[a][b][c] = 0.f;

    for (int kt = 0; kt < 6; ++kt) {
        int k0 = kt * 32;
#pragma unroll
        for (int it = 0; it < 4; ++it) {
            int fid = tid + it * 256;
            int ml = fid >> 3, kc = fid & 7;
            float4 v = *(const float4*)(A + (m0 + ml) * DIMM + k0 + kc * 4);
            As[kc * 4 + 0][ml] = v.x;
            As[kc * 4 + 1][ml] = v.y;
            As[kc * 4 + 2][ml] = v.z;
            As[kc * 4 + 3][ml] = v.w;
        }
#pragma unroll
        for (int it = 0; it < 2; ++it) {
            int fid = tid + it * 256;
            int nl = fid >> 3, kc = fid & 7;
            float4 v = *(const float4*)(W + (size_t)(n0 + nl) * DIMM + k0 + kc * 4);
            Bs[kc * 4 + 0][nl] = v.x;
            Bs[kc * 4 + 1][nl] = v.y;
            Bs[kc * 4 + 2][nl] = v.z;
            Bs[kc * 4 + 3][nl] = v.w;
        }
        __syncthreads();

#pragma unroll
        for (int kc = 0; kc < 4; ++kc) {
            int kr = kc * 8 + t;
            uint Ah[2][4], Al[2][4];
#pragma unroll
            for (int mt = 0; mt < 2; ++mt) {
                int mb = wm * 32 + mt * 16 + g;
                float f0 = As[kr][mb];
                float f1 = As[kr][mb + 8];
                float f2 = As[kr + 4][mb];
                float f3 = As[kr + 4][mb + 8];
                tf32_split(f0, Ah[mt][0], Al[mt][0]);
                tf32_split(f1, Ah[mt][1], Al[mt][1]);
                tf32_split(f2, Ah[mt][2], Al[mt][2]);
                tf32_split(f3, Ah[mt][3], Al[mt][3]);
            }
            uint Bh[4][2], Bl[4][2];
#pragma unroll
            for (int nt = 0; nt < 4; ++nt) {
                int nb = wn * 32 + nt * 8 + g;
                float f0 = Bs[kr][nb];
                float f1 = Bs[kr + 4][nb];
                tf32_split(f0, Bh[nt][0], Bl[nt][0]);
                tf32_split(f1, Bh[nt][1], Bl[nt][1]);
            }
#pragma unroll
            for (int mt = 0; mt < 2; ++mt)
#pragma unroll
                for (int nt = 0; nt < 4; ++nt) {
                    mma1688(acc[mt][nt], Ah[mt][0], Ah[mt][1], Ah[mt][2], Ah[mt][3],
                            Bh[nt][0], Bh[nt][1]);
                    mma1688(acc[mt][nt], Ah[mt][0], Ah[mt][1], Ah[mt][2], Ah[mt][3],
                            Bl[nt][0], Bl[nt][1]);
                    mma1688(acc[mt][nt], Al[mt][0], Al[mt][1], Al[mt][2], Al[mt][3],
                            Bh[nt][0], Bh[nt][1]);
                }
        }
        __syncthreads();
    }

#pragma unroll
    for (int mt = 0; mt < 2; ++mt) {
        int r0 = (int)m0 + wm * 32 + mt * 16 + g;
        int r1 = r0 + 8;
        int ib0 = r0 / N_TOK, in0 = r0 - ib0 * N_TOK;
        int ib1 = r1 / N_TOK, in1 = r1 - ib1 * N_TOK;
#pragma unroll
        for (int nt = 0; nt < 4; ++nt) {
            int c = n0 + wn * 32 + nt * 8 + 2 * t;
            float bv0 = bias[c], bv1 = bias[c + 1];
            if (mode == 1) {
                float2 v0 = make_float2(acc[mt][nt][0] + bv0, acc[mt][nt][1] + bv1);
                float2 v1 = make_float2(acc[mt][nt][2] + bv0, acc[mt][nt][3] + bv1);
                *(float2*)(outp + (size_t)r0 * DIMM + c) = v0;
                *(float2*)(outp + (size_t)r1 * DIMM + c) = v1;
            } else {
                int which = c / DIMM;
                int rem = c - which * DIMM;
                int hh = rem >> 5;
                int d0 = rem & 31;
                float qs = (which == 0) ? QS_LOG2E : 1.0f;
                float* dst = (which == 0) ? g_q : ((which == 1) ? g_k : g_v);
                size_t o0 = (((size_t)ib0 * NH + hh) * N_TOK + in0) * HD + d0;
                size_t o1 = (((size_t)ib1 * NH + hh) * N_TOK + in1) * HD + d0;
                float2 v0 = make_float2((acc[mt][nt][0] + bv0) * qs,
                                        (acc[mt][nt][1] + bv1) * qs);
                float2 v1 = make_float2((acc[mt][nt][2] + bv0) * qs,
                                        (acc[mt][nt][3] + bv1) * qs);
                *(float2*)(dst + o0) = v0;
                *(float2*)(dst + o1) = v1;
            }
        }
    }
}

/* ------------------------------------------------------------------ */
/* Tensor-core attention. One CTA per (b,h), 128 threads (4 warps),    */
/* 3 q-tiles of 128. K (hi/lo bf16, [key][d], pitch 20w) and V^T       */
/* (hi/lo bf16, [d][key], pitch 180w) staged once in smem (100KB).     */
/* S = QhKh+QhKl+QlKh (m16n8k16); softmax in registers (ex2, fused     */
/* bias+mask prefetched 1 chunk ahead); P hi/lo packed straight into   */
/* PV A-fragments; O = PhVh+PhVl+PlVh. Keys padded to 352 (bm=-inf).   */
/* ------------------------------------------------------------------ */
__global__ __launch_bounds__(128, 2) void attn_tc_kernel() {
    extern __shared__ __align__(16) uint smemu[];
    uint* Khs = smemu;                       /* 352*20 */
    uint* Kls = Khs + N_JPAD * KP;
    uint* Vhs = Kls + N_JPAD * KP;           /* 32*180 */
    uint* Vls = Vhs + 32 * VP;

    int tid = threadIdx.x;
    int bh = blockIdx.x;
    int hw = bh >> 2;
    int img = bh & 3;
    int hh = hw >> 6;
    int w = hw & 63;
    int bb = img * NWIN + w;

    size_t base = ((size_t)bb * NH + hh) * N_TOK * HD;

    /* ---- stage K (hi/lo) and V^T (hi/lo) ---- */
    {
        unsigned short* VhsS = (unsigned short*)Vhs;
        unsigned short* VlsS = (unsigned short*)Vls;
#pragma unroll
        for (int it = 0; it < 22; ++it) {
            int idx = tid + it * 128;        /* 0..2815 */
            int key = idx >> 3, dq = idx & 7;
            float4 kv = make_float4(0.f, 0.f, 0.f, 0.f);
            float4 vv = make_float4(0.f, 0.f, 0.f, 0.f);
            if (key < N_TOK) {
                kv = *(const float4*)(g_k + base + (size_t)key * HD + dq * 4);
                vv = *(const float4*)(g_v + base + (size_t)key * HD + dq * 4);
            }
            uint kh0, kl0, kh1, kl1;
            bfsplit2(kv.x, kv.y, kh0, kl0);
            bfsplit2(kv.z, kv.w, kh1, kl1);
            Khs[key * KP + dq * 2]     = kh0;
            Khs[key * KP + dq * 2 + 1] = kh1;
            Kls[key * KP + dq * 2]     = kl0;
            Kls[key * KP + dq * 2 + 1] = kl1;
            uint vh0, vl0, vh1, vl1;
            bfsplit2(vv.x, vv.y, vh0, vl0);
            bfsplit2(vv.z, vv.w, vh1, vl1);
            int d0 = dq * 4;
            VhsS[(d0 + 0) * (2 * VP) + key] = (unsigned short)(vh0 & 0xffff);
            VhsS[(d0 + 1) * (2 * VP) + key] = (unsigned short)(vh0 >> 16);
            VhsS[(d0 + 2) * (2 * VP) + key] = (unsigned short)(vh1 & 0xffff);
            VhsS[(d0 + 3) * (2 * VP) + key] = (unsigned short)(vh1 >> 16);
            VlsS[(d0 + 0) * (2 * VP) + key] = (unsigned short)(vl0 & 0xffff);
            VlsS[(d0 + 1) * (2 * VP) + key] = (unsigned short)(vl0 >> 16);
            VlsS[(d0 + 2) * (2 * VP) + key] = (unsigned short)(vl1 & 0xffff);
            VlsS[(d0 + 3) * (2 * VP) + key] = (unsigned short)(vl1 >> 16);
        }
    }
    __syncthreads();

    int lane = tid & 31, warp = tid >> 5;
    int g = lane >> 2, t = lane & 3;
    const float* pbm = g_bm + (size_t)hw * (N_JPAD * N_TOK);

    for (int qt = 0; qt < 3; ++qt) {
        int q0 = qt * 128;

        /* Q fragments (hi/lo), rows clamped for the qt=2 pad */
        uint Qh[2][2][4], Ql[2][2][4];
        int qg[2];
#pragma unroll
        for (int mt = 0; mt < 2; ++mt) {
            int r0 = q0 + warp * 32 + mt * 16 + g;
            qg[mt] = r0;
            int c0r = (r0 < N_TOK) ? r0 : (N_TOK - 1);
            int r1 = r0 + 8;
            int c1r = (r1 < N_TOK) ? r1 : (N_TOK - 1);
#pragma unroll
            for (int dc = 0; dc < 2; ++dc) {
                float2 f0 = *(const float2*)(g_q + base + (size_t)c0r * HD + 16 * dc + 2 * t);
                float2 f1 = *(const float2*)(g_q + base + (size_t)c1r * HD + 16 * dc + 2 * t);
                float2 f2 = *(const float2*)(g_q + base + (size_t)c0r * HD + 16 * dc + 2 * t + 8);
                float2 f3 = *(const float2*)(g_q + base + (size_t)c1r * HD + 16 * dc + 2 * t + 8);
                bfsplit2(f0.x, f0.y, Qh[mt][dc][0], Ql[mt][dc][0]);
                bfsplit2(f1.x, f1.y, Qh[mt][dc][1], Ql[mt][dc][1]);
                bfsplit2(f2.x, f2.y, Qh[mt][dc][2], Ql[mt][dc][2]);
                bfsplit2(f3.x, f3.y, Qh[mt][dc][3], Ql[mt][dc][3]);
            }
        }

        float o[2][4][4];
#pragma unroll
        for (int mt = 0; mt < 2; ++mt)
#pragma unroll
            for (int nd = 0; nd < 4; ++nd)
#pragma unroll
                for (int c = 0; c < 4; ++c) o[mt][nd][c] = 0.f;
        float lsum[2][2] = {{0.f, 0.f}, {0.f, 0.f}};

        /* bias prefetch (chunk 0) */
        float pf[2][2][4];
#pragma unroll
        for (int mt = 0; mt < 2; ++mt)
#pragma unroll
            for (int n8 = 0; n8 < 2; ++n8) {
                const float* bp = pbm + (size_t)(8 * n8 + 2 * t) * N_TOK + qg[mt];
                pf[mt][n8][0] = __ldg(bp);
                pf[mt][n8][1] = __ldg(bp + N_TOK);
                pf[mt][n8][2] = __ldg(bp + 8);
                pf[mt][n8][3] = __ldg(bp + N_TOK + 8);
            }

        for (int kc = 0; kc < 22; ++kc) {
            int kb = kc * 16;
            float cb[2][2][4];
#pragma unroll
            for (int mt = 0; mt < 2; ++mt)
#pragma unroll
                for (int n8 = 0; n8 < 2; ++n8)
#pragma unroll
                    for (int c = 0; c < 4; ++c) cb[mt][n8][c] = pf[mt][n8][c];

            int kbn = (kb + 16 <= 336) ? (kb + 16) : 336;
#pragma unroll
            for (int mt = 0; mt < 2; ++mt)
#pragma unroll
                for (int n8 = 0; n8 < 2; ++n8) {
                    const float* bp = pbm + (size_t)(kbn + 8 * n8 + 2 * t) * N_TOK + qg[mt];
                    pf[mt][n8][0] = __ldg(bp);
                    pf[mt][n8][1] = __ldg(bp + N_TOK);
                    pf[mt][n8][2] = __ldg(bp + 8);
                    pf[mt][n8][3] = __ldg(bp + N_TOK + 8);
                }

            /* K B-fragments */
            uint bKh[2][2][2], bKl[2][2][2];
#pragma unroll
            for (int n8 = 0; n8 < 2; ++n8) {
                const uint* krh = Khs + (kb + 8 * n8 + g) * KP;
                const uint* krl = Kls + (kb + 8 * n8 + g) * KP;
#pragma unroll
                for (int dc = 0; dc < 2; ++dc) {
                    bKh[n8][dc][0] = krh[8 * dc + t];
                    bKh[n8][dc][1] = krh[8 * dc + t + 4];
                    bKl[n8][dc][0] = krl[8 * dc + t];
                    bKl[n8][dc][1] = krl[8 * dc + t + 4];
                }
            }

            /* S = QK, softmax, pack P */
            uint aPh[2][4], aPl[2][4];
#pragma unroll
            for (int mt = 0; mt < 2; ++mt) {
#pragma unroll
                for (int n8 = 0; n8 < 2; ++n8) {
                    float s[4] = {0.f, 0.f, 0.f, 0.f};
#pragma unroll
                    for (int dc = 0; dc < 2; ++dc) {
                        mma_bf(s, Qh[mt][dc][0], Qh[mt][dc][1], Qh[mt][dc][2], Qh[mt][dc][3],
                               bKh[n8][dc][0], bKh[n8][dc][1]);
                        mma_bf(s, Qh[mt][dc][0], Qh[mt][dc][1], Qh[mt][dc][2], Qh[mt][dc][3],
                               bKl[n8][dc][0], bKl[n8][dc][1]);
                        mma_bf(s, Ql[mt][dc][0], Ql[mt][dc][1], Ql[mt][dc][2], Ql[mt][dc][3],
                               bKh[n8][dc][0], bKh[n8][dc][1]);
                    }
                    float p0 = ex2f(s[0] + cb[mt][n8][0]);
                    float p1 = ex2f(s[1] + cb[mt][n8][1]);
                    float p2 = ex2f(s[2] + cb[mt][n8][2]);
                    float p3 = ex2f(s[3] + cb[mt][n8][3]);
                    lsum[mt][0] += p0 + p1;
                    lsum[mt][1] += p2 + p3;
                    bfsplit2(p0, p1, aPh[mt][n8 * 2], aPl[mt][n8 * 2]);
                    bfsplit2(p2, p3, aPh[mt][n8 * 2 + 1], aPl[mt][n8 * 2 + 1]);
                }
            }

            /* O += P V */
#pragma unroll
            for (int nd = 0; nd < 4; ++nd) {
                const uint* vrh = Vhs + (nd * 8 + g) * VP;
                const uint* vrl = Vls + (nd * 8 + g) * VP;
                uint bh0 = vrh[kb / 2 + t];
                uint bh1 = vrh[kb / 2 + t + 4];
                uint bl0 = vrl[kb / 2 + t];
                uint bl1 = vrl[kb / 2 + t + 4];
#pragma unroll
                for (int mt = 0; mt < 2; ++mt) {
                    mma_bf(o[mt][nd], aPh[mt][0], aPh[mt][1], aPh[mt][2], aPh[mt][3], bh0, bh1);
                    mma_bf(o[mt][nd], aPh[mt][0], aPh[mt][1], aPh[mt][2], aPh[mt][3], bl0, bl1);
                    mma_bf(o[mt][nd], aPl[mt][0], aPl[mt][1], aPl[mt][2], aPl[mt][3], bh0, bh1);
                }
            }
        }

        /* epilogue: row sums (quad reduce) + store */
#pragma unroll
        for (int mt = 0; mt < 2; ++mt) {
            float lg = lsum[mt][0];
            lg += __shfl_xor_sync(0xffffffffu, lg, 1);
            lg += __shfl_xor_sync(0xffffffffu, lg, 2);
            float lg8 = lsum[mt][1];
            lg8 += __shfl_xor_sync(0xffffffffu, lg8, 1);
            lg8 += __shfl_xor_sync(0xffffffffu, lg8, 2);
            float ig = 1.0f / lg, ig8 = 1.0f / lg8;
            int r0 = qg[mt], r1 = qg[mt] + 8;
#pragma unroll
            for (int nd = 0; nd < 4; ++nd) {
                int d = nd * 8 + 2 * t;
                if (r0 < N_TOK) {
                    float2 v = make_float2(o[mt][nd][0] * ig, o[mt][nd][1] * ig);
                    *(float2*)(g_ao + ((size_t)bb * N_TOK + r0) * DIMM + hh * HD + d) = v;
                }
                if (r1 < N_TOK) {
                    float2 v = make_float2(o[mt][nd][2] * ig8, o[mt][nd][3] * ig8);
                    *(float2*)(g_ao + ((size_t)bb * N_TOK + r1) * DIMM + hh * HD + d) = v;
                }
            }
        }
        /* reset accumulators happens at loop top via redeclare */
    }
}

/* ------------------------------------------------------------------ */
extern "C" void kernel_launch(void* const* d_in, const int* in_sizes, int n_in,
                              void* d_out, int out_size) {
    const float* x      = (const float*)d_in[0];
    const float* mask   = (const float*)d_in[1];
    const float* qkv_w  = (const float*)d_in[2];
    const float* qkv_b  = (const float*)d_in[3];
    const float* rpb    = (const float*)d_in[4];
    const float* proj_w = (const float*)d_in[5];
    const float* proj_b = (const float*)d_in[6];
    float* out = (float*)d_out;

    const int smem_attn = (N_JPAD * KP * 2 + 32 * VP * 2) * 4;  /* 102400 B */
    cudaFuncSetAttribute(attn_tc_kernel,
                         cudaFuncAttributeMaxDynamicSharedMemorySize, smem_attn);

    transpose_mask_kernel<<<dim3(11, 11, NWIN), dim3(32, 8)>>>(mask);
    combine_bm_kernel<<<dim3(N_JPAD, NWIN), N_TOK>>>(rpb);
    gemm_tc_kernel<<<dim3(M_ROWS / 128, 9), 256>>>(x, qkv_w, qkv_b, nullptr, 0);
    attn_tc_kernel<<<BATCH * NH, 128, smem_attn>>>();
    gemm_tc_kernel<<<dim3(M_ROWS / 128, 3), 256>>>(nullptr, proj_w, proj_b, out, 1);
}